// round 3
// baseline (speedup 1.0000x reference)
#include <cuda_runtime.h>
#include <cuda_bf16.h>
#include <stdint.h>

#define NN 100000
#define NN_PAD 100096           // 782 * 128
#define NE 1600000
#define IN_DIM 128
#define HID_DIM 256
#define OUT_DIM 64

// ---------------- device scratch ----------------
__device__ __align__(16) int   g_deg_src[NN];
__device__ __align__(16) int   g_deg_dst[NN];
__device__ __align__(16) int   g_rowptr[NN + 1];
__device__ __align__(16) int   g_cursor[NN];
__device__ __align__(16) int   g_esrc[NE];          // edge src ids, bucketed by dst
__device__ __align__(16) float g_norm_src[NN];
__device__ __align__(16) float g_norm_dst[NN];
__device__ __align__(16) float g_xagg[(size_t)NN_PAD * IN_DIM];
__device__ __align__(16) __nv_bfloat16 g_hid_hi[(size_t)NN_PAD * HID_DIM];
__device__ __align__(16) __nv_bfloat16 g_hid_lo[(size_t)NN_PAD * HID_DIM];
__device__ __align__(16) float g_ypre[(size_t)NN * OUT_DIM];

__device__ __forceinline__ void split_bf16(float v, __nv_bfloat16& hi, __nv_bfloat16& lo) {
    hi = __float2bfloat16(v);
    lo = __float2bfloat16(v - __bfloat162float(hi));
}

#define MMA_BF16(d, a, b0, b1)                                                  \
    asm volatile("mma.sync.aligned.m16n8k16.row.col.f32.bf16.bf16.f32 "         \
                 "{%0,%1,%2,%3}, {%4,%5,%6,%7}, {%8,%9}, {%0,%1,%2,%3};"        \
                 : "+f"(d[0]), "+f"(d[1]), "+f"(d[2]), "+f"(d[3])               \
                 : "r"(a[0]), "r"(a[1]), "r"(a[2]), "r"(a[3]), "r"(b0), "r"(b1))

// ---------------- init: zero degree counters + pad rows ----------------
__global__ void k_init() {
    int i = blockIdx.x * blockDim.x + threadIdx.x;
    int stride = gridDim.x * blockDim.x;
    for (int j = i; j < NN; j += stride) { g_deg_src[j] = 0; g_deg_dst[j] = 0; }
    // xagg pad rows (read by gemm1 A tiles) must be zero
    const int xpad4 = (NN_PAD - NN) * (IN_DIM / 4);
    float4* xp = reinterpret_cast<float4*>(g_xagg + (size_t)NN * IN_DIM);
    const float4 z = make_float4(0.f, 0.f, 0.f, 0.f);
    for (int j = i; j < xpad4; j += stride) xp[j] = z;
    // hidden pad rows (read by gemm2 A tiles) must be zero
    const int hpad4 = (NN_PAD - NN) * (HID_DIM / 8);   // uint4 = 8 bf16
    uint4* hh = reinterpret_cast<uint4*>(g_hid_hi + (size_t)NN * HID_DIM);
    uint4* hl = reinterpret_cast<uint4*>(g_hid_lo + (size_t)NN * HID_DIM);
    const uint4 z4 = make_uint4(0u, 0u, 0u, 0u);
    for (int j = i; j < hpad4; j += stride) { hh[j] = z4; hl[j] = z4; }
}

// ---------------- degrees (int atomics) ----------------
__global__ void k_degree(const int* __restrict__ src, const int* __restrict__ dst, int n_edges) {
    int i = blockIdx.x * blockDim.x + threadIdx.x;
    int stride = gridDim.x * blockDim.x;
    for (int e = i; e < n_edges; e += stride) {
        atomicAdd(&g_deg_src[src[e]], 1);
        atomicAdd(&g_deg_dst[dst[e]], 1);
    }
}

// ---------------- norms ----------------
__global__ void k_norm(int n_nodes) {
    int i = blockIdx.x * blockDim.x + threadIdx.x;
    if (i < n_nodes) {
        g_norm_src[i] = rsqrtf((float)max(g_deg_src[i], 1));
        g_norm_dst[i] = rsqrtf((float)max(g_deg_dst[i], 1));
    }
}

// ---------------- single-block exclusive scan of dst degrees -> rowptr, cursor ----------------
__global__ __launch_bounds__(1024) void k_scan() {
    __shared__ int sh[1024];
    const int tid = threadIdx.x;
    const int per = (NN + 1023) / 1024;   // 98
    const int base = tid * per;
    int sum = 0;
    for (int i = 0; i < per; i++) {
        int idx = base + i;
        if (idx < NN) sum += g_deg_dst[idx];
    }
    sh[tid] = sum;
    __syncthreads();
    // inclusive Hillis-Steele scan
    for (int off = 1; off < 1024; off <<= 1) {
        int t = (tid >= off) ? sh[tid - off] : 0;
        __syncthreads();
        sh[tid] += t;
        __syncthreads();
    }
    int run = sh[tid] - sum;   // exclusive offset for this thread's segment
    for (int i = 0; i < per; i++) {
        int idx = base + i;
        if (idx < NN) {
            g_rowptr[idx] = run;
            g_cursor[idx] = run;
            run += g_deg_dst[idx];
        }
    }
    if (tid == 1023) g_rowptr[NN] = run;
}

// ---------------- scatter edges into dst buckets ----------------
__global__ void k_scatter(const int* __restrict__ src, const int* __restrict__ dst, int n_edges) {
    int i = blockIdx.x * blockDim.x + threadIdx.x;
    int stride = gridDim.x * blockDim.x;
    for (int e = i; e < n_edges; e += stride) {
        int d = dst[e];
        int pos = atomicAdd(&g_cursor[d], 1);
        g_esrc[pos] = src[e];
    }
}

// ---------------- SpMM1 (CSR): xagg[d] = norm_dst[d] * sum_e h[src_e]*norm_src[src_e] ----------------
// warp per dst node, 128 feats = 32 lanes x float4
__global__ void k_spmm1(const float* __restrict__ h, int n_nodes) {
    int node = blockIdx.x * 8 + (threadIdx.x >> 5);
    if (node >= n_nodes) return;
    int lane = threadIdx.x & 31;
    int e = g_rowptr[node];
    const int end = g_rowptr[node + 1];
    const float4* h4 = reinterpret_cast<const float4*>(h);
    float4 acc = make_float4(0.f, 0.f, 0.f, 0.f);
    for (; e + 4 <= end; e += 4) {
        int s0 = g_esrc[e], s1 = g_esrc[e + 1], s2 = g_esrc[e + 2], s3 = g_esrc[e + 3];
        float n0 = g_norm_src[s0], n1 = g_norm_src[s1], n2 = g_norm_src[s2], n3 = g_norm_src[s3];
        float4 v0 = h4[(size_t)s0 * 32 + lane];
        float4 v1 = h4[(size_t)s1 * 32 + lane];
        float4 v2 = h4[(size_t)s2 * 32 + lane];
        float4 v3 = h4[(size_t)s3 * 32 + lane];
        acc.x += v0.x * n0 + v1.x * n1 + v2.x * n2 + v3.x * n3;
        acc.y += v0.y * n0 + v1.y * n1 + v2.y * n2 + v3.y * n3;
        acc.z += v0.z * n0 + v1.z * n1 + v2.z * n2 + v3.z * n3;
        acc.w += v0.w * n0 + v1.w * n1 + v2.w * n2 + v3.w * n3;
    }
    for (; e < end; e++) {
        int s = g_esrc[e];
        float ns = g_norm_src[s];
        float4 v = h4[(size_t)s * 32 + lane];
        acc.x += v.x * ns; acc.y += v.y * ns; acc.z += v.z * ns; acc.w += v.w * ns;
    }
    float nd = g_norm_dst[node];
    acc.x *= nd; acc.y *= nd; acc.z *= nd; acc.w *= nd;
    reinterpret_cast<float4*>(g_xagg)[(size_t)node * 32 + lane] = acc;
}

// ---------------- GEMM tiles ----------------
#define BM 128
#define BN 64
#define BK 32
#define KPAD 40

// GEMM1: hidden = relu(xagg @ W1 + b1) * clip(p,0,1); split-bf16 store
__global__ __launch_bounds__(256) void k_gemm1(const float* __restrict__ W1,
                                               const float* __restrict__ b1,
                                               const float* __restrict__ p,
                                               int n_nodes) {
    __shared__ __align__(16) __nv_bfloat16 As_hi[BM * KPAD];
    __shared__ __align__(16) __nv_bfloat16 As_lo[BM * KPAD];
    __shared__ __align__(16) __nv_bfloat16 Bs_hi[BN * KPAD];
    __shared__ __align__(16) __nv_bfloat16 Bs_lo[BN * KPAD];

    const int m0 = blockIdx.x * BM;
    const int n0 = blockIdx.y * BN;
    const int tid = threadIdx.x;
    const int lane = tid & 31;
    const int wid = tid >> 5;
    const int warp_m = wid >> 2;
    const int warp_n = wid & 3;

    float acc[4][2][4];
    #pragma unroll
    for (int i = 0; i < 4; i++)
        #pragma unroll
        for (int j = 0; j < 2; j++)
            #pragma unroll
            for (int q = 0; q < 4; q++) acc[i][j][q] = 0.f;

    for (int k0 = 0; k0 < IN_DIM; k0 += BK) {
        #pragma unroll
        for (int i = 0; i < 4; i++) {
            int row = (tid >> 3) + 32 * i;
            int kk = (tid & 7) * 4;
            float4 v = *reinterpret_cast<const float4*>(&g_xagg[(size_t)(m0 + row) * IN_DIM + k0 + kk]);
            __nv_bfloat16 h0, l0, h1, l1, h2, l2, h3, l3;
            split_bf16(v.x, h0, l0); split_bf16(v.y, h1, l1);
            split_bf16(v.z, h2, l2); split_bf16(v.w, h3, l3);
            *reinterpret_cast<__nv_bfloat162*>(&As_hi[row * KPAD + kk])     = __nv_bfloat162(h0, h1);
            *reinterpret_cast<__nv_bfloat162*>(&As_hi[row * KPAD + kk + 2]) = __nv_bfloat162(h2, h3);
            *reinterpret_cast<__nv_bfloat162*>(&As_lo[row * KPAD + kk])     = __nv_bfloat162(l0, l1);
            *reinterpret_cast<__nv_bfloat162*>(&As_lo[row * KPAD + kk + 2]) = __nv_bfloat162(l2, l3);
        }
        for (int i = tid; i < BK * BN; i += 256) {
            int k = i >> 6, n = i & 63;
            float v = W1[(size_t)(k0 + k) * HID_DIM + n0 + n];
            __nv_bfloat16 hi, lo;
            split_bf16(v, hi, lo);
            Bs_hi[n * KPAD + k] = hi;
            Bs_lo[n * KPAD + k] = lo;
        }
        __syncthreads();

        #pragma unroll
        for (int ks = 0; ks < 2; ks++) {
            const int kc = ks * 16 + 2 * (lane & 3);
            uint32_t ah[4][4], al[4][4];
            #pragma unroll
            for (int i = 0; i < 4; i++) {
                int r = warp_m * 64 + i * 16 + (lane >> 2);
                ah[i][0] = *reinterpret_cast<uint32_t*>(&As_hi[r * KPAD + kc]);
                ah[i][1] = *reinterpret_cast<uint32_t*>(&As_hi[(r + 8) * KPAD + kc]);
                ah[i][2] = *reinterpret_cast<uint32_t*>(&As_hi[r * KPAD + kc + 8]);
                ah[i][3] = *reinterpret_cast<uint32_t*>(&As_hi[(r + 8) * KPAD + kc + 8]);
                al[i][0] = *reinterpret_cast<uint32_t*>(&As_lo[r * KPAD + kc]);
                al[i][1] = *reinterpret_cast<uint32_t*>(&As_lo[(r + 8) * KPAD + kc]);
                al[i][2] = *reinterpret_cast<uint32_t*>(&As_lo[r * KPAD + kc + 8]);
                al[i][3] = *reinterpret_cast<uint32_t*>(&As_lo[(r + 8) * KPAD + kc + 8]);
            }
            #pragma unroll
            for (int j = 0; j < 2; j++) {
                int c = warp_n * 16 + j * 8 + (lane >> 2);
                uint32_t bh0 = *reinterpret_cast<uint32_t*>(&Bs_hi[c * KPAD + kc]);
                uint32_t bh1 = *reinterpret_cast<uint32_t*>(&Bs_hi[c * KPAD + kc + 8]);
                uint32_t bl0 = *reinterpret_cast<uint32_t*>(&Bs_lo[c * KPAD + kc]);
                uint32_t bl1 = *reinterpret_cast<uint32_t*>(&Bs_lo[c * KPAD + kc + 8]);
                #pragma unroll
                for (int i = 0; i < 4; i++) {
                    MMA_BF16(acc[i][j], ah[i], bh0, bh1);
                    MMA_BF16(acc[i][j], ah[i], bl0, bl1);
                    MMA_BF16(acc[i][j], al[i], bh0, bh1);
                }
            }
        }
        __syncthreads();
    }

    #pragma unroll
    for (int i = 0; i < 4; i++) {
        int r = warp_m * 64 + i * 16 + (lane >> 2);
        #pragma unroll
        for (int j = 0; j < 2; j++) {
            int c0 = n0 + warp_n * 16 + j * 8 + 2 * (lane & 3);
            float bb0 = b1[c0], bb1 = b1[c0 + 1];
            float p0 = fminf(fmaxf(p[c0], 0.f), 1.f);
            float p1 = fminf(fmaxf(p[c0 + 1], 0.f), 1.f);
            #pragma unroll
            for (int hrow = 0; hrow < 2; hrow++) {
                int grow = m0 + r + 8 * hrow;
                if (grow >= n_nodes) continue;
                float v0 = fmaxf(acc[i][j][2 * hrow + 0] + bb0, 0.f) * p0;
                float v1 = fmaxf(acc[i][j][2 * hrow + 1] + bb1, 0.f) * p1;
                __nv_bfloat16 h0, l0, h1, l1;
                split_bf16(v0, h0, l0);
                split_bf16(v1, h1, l1);
                *reinterpret_cast<__nv_bfloat162*>(&g_hid_hi[(size_t)grow * HID_DIM + c0]) = __nv_bfloat162(h0, h1);
                *reinterpret_cast<__nv_bfloat162*>(&g_hid_lo[(size_t)grow * HID_DIM + c0]) = __nv_bfloat162(l0, l1);
            }
        }
    }
}

// GEMM2: ypre = (hidden @ W2) * norm_src[row]
__global__ __launch_bounds__(256) void k_gemm2(const float* __restrict__ W2, int n_nodes) {
    __shared__ __align__(16) __nv_bfloat16 As_hi[BM * KPAD];
    __shared__ __align__(16) __nv_bfloat16 As_lo[BM * KPAD];
    __shared__ __align__(16) __nv_bfloat16 Bs_hi[BN * KPAD];
    __shared__ __align__(16) __nv_bfloat16 Bs_lo[BN * KPAD];

    const int m0 = blockIdx.x * BM;
    const int tid = threadIdx.x;
    const int lane = tid & 31;
    const int wid = tid >> 5;
    const int warp_m = wid >> 2;
    const int warp_n = wid & 3;

    float acc[4][2][4];
    #pragma unroll
    for (int i = 0; i < 4; i++)
        #pragma unroll
        for (int j = 0; j < 2; j++)
            #pragma unroll
            for (int q = 0; q < 4; q++) acc[i][j][q] = 0.f;

    for (int k0 = 0; k0 < HID_DIM; k0 += BK) {
        #pragma unroll
        for (int i = 0; i < 2; i++) {
            int idx = tid + 256 * i;
            int row = idx >> 2;
            int q = idx & 3;
            uint4 vh = *reinterpret_cast<const uint4*>(&g_hid_hi[(size_t)(m0 + row) * HID_DIM + k0 + 8 * q]);
            uint4 vl = *reinterpret_cast<const uint4*>(&g_hid_lo[(size_t)(m0 + row) * HID_DIM + k0 + 8 * q]);
            *reinterpret_cast<uint4*>(&As_hi[row * KPAD + 8 * q]) = vh;
            *reinterpret_cast<uint4*>(&As_lo[row * KPAD + 8 * q]) = vl;
        }
        for (int i = tid; i < BK * BN; i += 256) {
            int k = i >> 6, n = i & 63;
            float v = W2[(size_t)(k0 + k) * OUT_DIM + n];
            __nv_bfloat16 hi, lo;
            split_bf16(v, hi, lo);
            Bs_hi[n * KPAD + k] = hi;
            Bs_lo[n * KPAD + k] = lo;
        }
        __syncthreads();

        #pragma unroll
        for (int ks = 0; ks < 2; ks++) {
            const int kc = ks * 16 + 2 * (lane & 3);
            uint32_t ah[4][4], al[4][4];
            #pragma unroll
            for (int i = 0; i < 4; i++) {
                int r = warp_m * 64 + i * 16 + (lane >> 2);
                ah[i][0] = *reinterpret_cast<uint32_t*>(&As_hi[r * KPAD + kc]);
                ah[i][1] = *reinterpret_cast<uint32_t*>(&As_hi[(r + 8) * KPAD + kc]);
                ah[i][2] = *reinterpret_cast<uint32_t*>(&As_hi[r * KPAD + kc + 8]);
                ah[i][3] = *reinterpret_cast<uint32_t*>(&As_hi[(r + 8) * KPAD + kc + 8]);
                al[i][0] = *reinterpret_cast<uint32_t*>(&As_lo[r * KPAD + kc]);
                al[i][1] = *reinterpret_cast<uint32_t*>(&As_lo[(r + 8) * KPAD + kc]);
                al[i][2] = *reinterpret_cast<uint32_t*>(&As_lo[r * KPAD + kc + 8]);
                al[i][3] = *reinterpret_cast<uint32_t*>(&As_lo[(r + 8) * KPAD + kc + 8]);
            }
            #pragma unroll
            for (int j = 0; j < 2; j++) {
                int c = warp_n * 16 + j * 8 + (lane >> 2);
                uint32_t bh0 = *reinterpret_cast<uint32_t*>(&Bs_hi[c * KPAD + kc]);
                uint32_t bh1 = *reinterpret_cast<uint32_t*>(&Bs_hi[c * KPAD + kc + 8]);
                uint32_t bl0 = *reinterpret_cast<uint32_t*>(&Bs_lo[c * KPAD + kc]);
                uint32_t bl1 = *reinterpret_cast<uint32_t*>(&Bs_lo[c * KPAD + kc + 8]);
                #pragma unroll
                for (int i = 0; i < 4; i++) {
                    MMA_BF16(acc[i][j], ah[i], bh0, bh1);
                    MMA_BF16(acc[i][j], ah[i], bl0, bl1);
                    MMA_BF16(acc[i][j], al[i], bh0, bh1);
                }
            }
        }
        __syncthreads();
    }

    #pragma unroll
    for (int i = 0; i < 4; i++) {
        int r = warp_m * 64 + i * 16 + (lane >> 2);
        #pragma unroll
        for (int j = 0; j < 2; j++) {
            int c0 = warp_n * 16 + j * 8 + 2 * (lane & 3);
            #pragma unroll
            for (int hrow = 0; hrow < 2; hrow++) {
                int grow = m0 + r + 8 * hrow;
                if (grow >= n_nodes) continue;
                float ns = g_norm_src[grow];
                float2 v;
                v.x = acc[i][j][2 * hrow + 0] * ns;
                v.y = acc[i][j][2 * hrow + 1] * ns;
                *reinterpret_cast<float2*>(&g_ypre[(size_t)grow * OUT_DIM + c0]) = v;
            }
        }
    }
}

// ---------------- SpMM2 (CSR, fused final): out[d] = norm_dst[d]*sum ypre[src_e] + b2 ----------------
// warp per dst node, 64 feats = 32 lanes x float2
__global__ void k_spmm2(float* __restrict__ out, const float* __restrict__ b2, int n_nodes) {
    int node = blockIdx.x * 8 + (threadIdx.x >> 5);
    if (node >= n_nodes) return;
    int lane = threadIdx.x & 31;
    int e = g_rowptr[node];
    const int end = g_rowptr[node + 1];
    const float2* y2 = reinterpret_cast<const float2*>(g_ypre);
    float2 acc = make_float2(0.f, 0.f);
    for (; e + 4 <= end; e += 4) {
        int s0 = g_esrc[e], s1 = g_esrc[e + 1], s2 = g_esrc[e + 2], s3 = g_esrc[e + 3];
        float2 v0 = y2[(size_t)s0 * 32 + lane];
        float2 v1 = y2[(size_t)s1 * 32 + lane];
        float2 v2 = y2[(size_t)s2 * 32 + lane];
        float2 v3 = y2[(size_t)s3 * 32 + lane];
        acc.x += v0.x + v1.x + v2.x + v3.x;
        acc.y += v0.y + v1.y + v2.y + v3.y;
    }
    for (; e < end; e++) {
        int s = g_esrc[e];
        float2 v = y2[(size_t)s * 32 + lane];
        acc.x += v.x; acc.y += v.y;
    }
    float nd = g_norm_dst[node];
    float2 bb = reinterpret_cast<const float2*>(b2)[lane];
    float2 o;
    o.x = acc.x * nd + bb.x;
    o.y = acc.y * nd + bb.y;
    reinterpret_cast<float2*>(out)[(size_t)node * 32 + lane] = o;
}

// ---------------- launch ----------------
extern "C" void kernel_launch(void* const* d_in, const int* in_sizes, int n_in,
                              void* d_out, int out_size) {
    const float* h  = (const float*)d_in[0];
    const float* W1 = (const float*)d_in[1];
    const float* b1 = (const float*)d_in[2];
    const float* W2 = (const float*)d_in[3];
    const float* b2 = (const float*)d_in[4];
    const float* p  = (const float*)d_in[5];
    const int* src  = (const int*)d_in[6];
    const int* dst  = (const int*)d_in[7];

    const int n_nodes = in_sizes[0] / IN_DIM;   // 100000
    const int n_edges = in_sizes[6];            // 1600000
    float* out = (float*)d_out;

    k_init<<<1024, 256>>>();
    k_degree<<<(n_edges + 1023) / 1024, 256>>>(src, dst, n_edges);
    k_scan<<<1, 1024>>>();
    k_norm<<<(n_nodes + 255) / 256, 256>>>(n_nodes);
    k_scatter<<<(n_edges + 1023) / 1024, 256>>>(src, dst, n_edges);

    k_spmm1<<<(n_nodes + 7) / 8, 256>>>(h, n_nodes);
    {
        dim3 grid(NN_PAD / BM, HID_DIM / BN);
        k_gemm1<<<grid, 256>>>(W1, b1, p, n_nodes);
    }
    {
        dim3 grid(NN_PAD / BM, 1);
        k_gemm2<<<grid, 256>>>(W2, n_nodes);
    }
    k_spmm2<<<(n_nodes + 7) / 8, 256>>>(out, b2, n_nodes);
}